// round 15
// baseline (speedup 1.0000x reference)
#include <cuda_runtime.h>
#include <cstdint>

// ---------------------------------------------------------------------------
// Problem constants
// ---------------------------------------------------------------------------
#define BB 32
#define LL 256
#define SS 128
#define AA 16
#define RR 4
#define M_TOK 8192        // B*L
#define K0 132            // S + R
#define K0P 144           // padded to /16 (guard-free A loop)
#define D1 2112
#define D2 4224
#define D3 8448
#define D4 4224
#define D5 64

// GEMM geometry: CTA 128x128, BK=16, 8 warps (4x2) of 32x64.
// A: activations as f16 hi/lo planes [m][k] (written by producer epilogue).
// B: weights as k-pair-interleaved f16 planes Wp[k/2][n].
// Mainloop = pure LDS.32 + 3x m16n8k16.f16 MMA (hi*hi + lo*hi + hi*lo).
#define BK 16
#define A_PITCH 24                        // f16 per A smem row (16 + 8 pad)
#define A_PL_BYTES (128 * A_PITCH * 2)    // 6144 per plane
#define BP_PITCH 132                      // uint32 per B pair-row (128 + 4 pad)
#define BP_BYTES (8 * BP_PITCH * 4)       // 4224 per plane
#define STAGE_BYTES (2 * A_PL_BYTES + 2 * BP_BYTES)  // 20736
#define NSTAGE 4
#define SMB (NSTAGE * STAGE_BYTES)        // 82944

// Pair-plane offsets (uint32 elements), layout [K/2][N]
#define PO1 0
#define PO2 152064                        // + 72*2112
#define PO3 4612608                       // + 1056*4224
#define PO4 22454784                      // + 2112*8448
#define PO5 40296960                      // + 4224*4224
#define PTOT 40432128                     // + 2112*64

// ---------------------------------------------------------------------------
// Scratch (static device globals; no allocation at runtime)
// ---------------------------------------------------------------------------
__device__ uint16_t g_xh[M_TOK * K0P];
__device__ uint16_t g_xl[M_TOK * K0P];
__device__ uint16_t g_h1[M_TOK * D1];
__device__ uint16_t g_l1[M_TOK * D1];
__device__ uint16_t g_h2[M_TOK * D2];
__device__ uint16_t g_l2[M_TOK * D2];
__device__ uint16_t g_h3[M_TOK * D3];
__device__ uint16_t g_l3[M_TOK * D3];
__device__ uint16_t g_h4[M_TOK * D4];
__device__ uint16_t g_l4[M_TOK * D4];
__device__ uint32_t g_wph[PTOT];
__device__ uint32_t g_wpl[PTOT];

// ---------------------------------------------------------------------------
// Helpers
// ---------------------------------------------------------------------------
__device__ __forceinline__ uint32_t smem_u32(const void* p) {
    uint32_t a;
    asm("{ .reg .u64 t; cvta.to.shared.u64 t, %1; cvt.u32.u64 %0, t; }" : "=r"(a) : "l"(p));
    return a;
}

__device__ __forceinline__ void cp16(uint32_t dst, const void* src, int pred16) {
    asm volatile("cp.async.cg.shared.global [%0], [%1], 16, %2;"
                 :: "r"(dst), "l"(src), "r"(pred16) : "memory");
}
#define CP_COMMIT() asm volatile("cp.async.commit_group;" ::: "memory")
#define CP_WAIT2()  asm volatile("cp.async.wait_group 2;" ::: "memory")

// exact 11-bit-mantissa hi by mask-truncation (fp16-exact)
__device__ __forceinline__ float hi_of(float x) {
    return __uint_as_float(__float_as_uint(x) & 0xFFFFE000u);
}
// pack two f32 into f16x2: low half = x0, high half = x1
__device__ __forceinline__ uint32_t pk16(float x1, float x0) {
    uint32_t r;
    asm("cvt.rn.f16x2.f32 %0, %1, %2;" : "=r"(r) : "f"(x1), "f"(x0));
    return r;
}

__device__ __forceinline__ void mma16f(float* c, const uint32_t* a, const uint32_t* b) {
    asm volatile(
        "mma.sync.aligned.m16n8k16.row.col.f32.f16.f16.f32 "
        "{%0,%1,%2,%3},{%4,%5,%6,%7},{%8,%9},{%0,%1,%2,%3};\n"
        : "+f"(c[0]), "+f"(c[1]), "+f"(c[2]), "+f"(c[3])
        : "r"(a[0]), "r"(a[1]), "r"(a[2]), "r"(a[3]), "r"(b[0]), "r"(b[1]));
}

// ---------------------------------------------------------------------------
// Weight pair-split: W[k][n] f32 -> Ph/Pl[k2][n] uint32 (f16 pair (2k2, 2k2+1))
// ---------------------------------------------------------------------------
__global__ void k_wpair(const float* __restrict__ W, uint32_t* __restrict__ Ph,
                        uint32_t* __restrict__ Pl, int KW, int N, long total) {
    long idx = (long)blockIdx.x * blockDim.x + threadIdx.x;  // over K2*N
    if (idx >= total) return;
    int k2 = (int)(idx / N);
    int n  = (int)(idx - (long)k2 * N);
    int k0 = 2 * k2, k1 = 2 * k2 + 1;
    float w0 = (k0 < KW) ? W[(long)k0 * N + n] : 0.0f;
    float w1 = (k1 < KW) ? W[(long)k1 * N + n] : 0.0f;
    float h0 = hi_of(w0), h1 = hi_of(w1);
    Ph[idx] = pk16(h1, h0);
    Pl[idx] = pk16(w1 - h1, w0 - h0);
}

// ---------------------------------------------------------------------------
// Concat + split: x0 planes [row][144]; 0:128 state, 128:132 pref, 132:144 = 0
// ---------------------------------------------------------------------------
__global__ void k_concat(const float* __restrict__ st, const float* __restrict__ pf,
                         uint16_t* __restrict__ xh, uint16_t* __restrict__ xl) {
    int idx = blockIdx.x * blockDim.x + threadIdx.x;
    if (idx >= M_TOK * K0P) return;
    int row = idx / K0P;
    int c   = idx - row * K0P;
    float v;
    if (c < SS)       v = st[row * SS + c];
    else if (c < K0)  v = pf[row * RR + (c - SS)];
    else              v = 0.0f;
    float h = hi_of(v);
    uint16_t hb, lb;
    asm("cvt.rn.f16.f32 %0, %1;" : "=h"(hb) : "f"(h));
    asm("cvt.rn.f16.f32 %0, %1;" : "=h"(lb) : "f"(v - h));
    xh[idx] = hb;
    xl[idx] = lb;
}

// ---------------------------------------------------------------------------
// GEMM: out = act(A @ W + bias)
// A: f16 hi/lo planes [m][KA]; B: f16 pair planes [K/2][N]. KA multiple of 16.
// OUT16: write f16 hi/lo activation planes; else f32 C.
// ---------------------------------------------------------------------------
template <bool RELU, bool OUT16>
__global__ __launch_bounds__(256, 2)
void k_gemm(const uint16_t* __restrict__ Ah, const uint16_t* __restrict__ Al,
            const uint32_t* __restrict__ Bph, const uint32_t* __restrict__ Bpl,
            const float* __restrict__ bias,
            uint16_t* __restrict__ Oh, uint16_t* __restrict__ Ol,
            float* __restrict__ C, int N, int KA)
{
    extern __shared__ char smem[];
    const uint32_t sb = smem_u32(smem);

    const int tid  = threadIdx.x;
    const int bm   = blockIdx.y * 128;
    const int n0   = blockIdx.x * 128;
    const int lane = tid & 31;
    const int wid  = tid >> 5;
    const int wm   = wid & 3;          // 0..3 -> 32 rows each
    const int wn   = wid >> 2;         // 0..1 -> 64 cols each
    const int grp  = lane >> 2;
    const int tig  = lane & 3;

    // ---- cp.async load mappings ----
    // A: thread -> row tid>>1, plane tid&1; 32B contiguous per row per plane
    const int ar = tid >> 1;
    const int ap = tid & 1;
    // B: 8 pair-rows x 128n (uint32); thread -> row tid>>5, chunk tid&31
    const int b_r = tid >> 5;
    const int b_c = tid & 31;

    const uint16_t* Asrc = (ap ? Al : Ah) + (long)(bm + ar) * KA;
    const uint32_t a_dst = ap * A_PL_BYTES + ar * (A_PITCH * 2);
    const int  n_okc = (n0 + b_c * 4 + 4 <= N) ? 16 : 0;   // N % 4 == 0 always

    const int T = KA >> 4;

    auto load_stage = [&](int t, int slot) {
        uint32_t st = sb + slot * STAGE_BYTES;
        // A planes (f16, guard-free: KA multiple of 16, buffers padded)
        {
            uint32_t d = st + a_dst;
            const uint16_t* s = Asrc + t * 16;
            cp16(d,      s,     16);
            cp16(d + 16, s + 8, 16);
        }
        // B pair planes (hi, lo)
        {
            long src = (long)(t * 8 + b_r) * N + n0 + b_c * 4;
            uint32_t d = st + 2 * A_PL_BYTES + (b_r * BP_PITCH + b_c * 4) * 4;
            cp16(d,            Bph + src, n_okc);
            cp16(d + BP_BYTES, Bpl + src, n_okc);
        }
    };

    float c[2][8][4];
#pragma unroll
    for (int mt = 0; mt < 2; mt++)
#pragma unroll
        for (int nt = 0; nt < 8; nt++)
#pragma unroll
            for (int j = 0; j < 4; j++) c[mt][nt][j] = 0.0f;

    // prologue: stages 0..2
#pragma unroll
    for (int s = 0; s < NSTAGE - 1; s++) {
        if (s < T) load_stage(s, s);
        CP_COMMIT();
    }

    for (int t = 0; t < T; t++) {
        CP_WAIT2();
        __syncthreads();
        {
            int lt = t + NSTAGE - 1;
            if (lt < T) load_stage(lt, lt & (NSTAGE - 1));
            CP_COMMIT();
        }
        const int slot = t & (NSTAGE - 1);
        const char*     sAH = smem + slot * STAGE_BYTES;
        const char*     sAL = sAH + A_PL_BYTES;
        const uint32_t* BHs = (const uint32_t*)(sAH + 2 * A_PL_BYTES);
        const uint32_t* BLs = BHs + 8 * BP_PITCH;

        // ---- A fragments: pure LDS.32 (banks 12*grp+tig, all distinct) ----
        uint32_t aH[2][4], aL[2][4];
#pragma unroll
        for (int mt = 0; mt < 2; mt++) {
            int R = wm * 32 + mt * 16 + grp;
#pragma unroll
            for (int kp = 0; kp < 2; kp++) {
#pragma unroll
                for (int rr = 0; rr < 2; rr++) {
                    int off = (R + 8 * rr) * (A_PITCH * 2) + kp * 16 + tig * 4;
                    aH[mt][kp * 2 + rr] = *(const uint32_t*)(sAH + off);
                    aL[mt][kp * 2 + rr] = *(const uint32_t*)(sAL + off);
                }
            }
        }

        // ---- B fragments (pure LDS.32) + 3-term MMAs ----
#pragma unroll
        for (int nt = 0; nt < 8; nt++) {
            int cb = wn * 64 + nt * 8 + grp;
            uint32_t bH[2], bL[2];
            bH[0] = BHs[tig * BP_PITCH + cb];
            bH[1] = BHs[(4 + tig) * BP_PITCH + cb];
            bL[0] = BLs[tig * BP_PITCH + cb];
            bL[1] = BLs[(4 + tig) * BP_PITCH + cb];
            mma16f(c[0][nt], aH[0], bH);   // hi*hi
            mma16f(c[0][nt], aL[0], bH);   // lo*hi
            mma16f(c[0][nt], aH[0], bL);   // hi*lo
            mma16f(c[1][nt], aH[1], bH);
            mma16f(c[1][nt], aL[1], bH);
            mma16f(c[1][nt], aH[1], bL);
        }
    }

    // epilogue: bias (+ relu); OUT16 -> f16 hi/lo planes, else f32
#pragma unroll
    for (int mt = 0; mt < 2; mt++) {
        int r = bm + wm * 32 + mt * 16 + grp;
#pragma unroll
        for (int nt = 0; nt < 8; nt++) {
            int col = n0 + wn * 64 + nt * 8 + tig * 2;
            if (col < N) {
                float bv0 = bias[col], bv1 = bias[col + 1];
                float v0 = c[mt][nt][0] + bv0;
                float v1 = c[mt][nt][1] + bv1;
                float v2 = c[mt][nt][2] + bv0;
                float v3 = c[mt][nt][3] + bv1;
                if (RELU) {
                    v0 = fmaxf(v0, 0.f); v1 = fmaxf(v1, 0.f);
                    v2 = fmaxf(v2, 0.f); v3 = fmaxf(v3, 0.f);
                }
                if (OUT16) {
                    float h0 = hi_of(v0), h1 = hi_of(v1);
                    float h2 = hi_of(v2), h3 = hi_of(v3);
                    long o0 = (long)r * N + col;         // even
                    long o1 = (long)(r + 8) * N + col;
                    *(uint32_t*)(Oh + o0) = pk16(h1, h0);
                    *(uint32_t*)(Ol + o0) = pk16(v1 - h1, v0 - h0);
                    *(uint32_t*)(Oh + o1) = pk16(h3, h2);
                    *(uint32_t*)(Ol + o1) = pk16(v3 - h3, v2 - h2);
                } else {
                    C[(long)r * N + col]           = v0;
                    C[(long)r * N + col + 1]       = v1;
                    C[(long)(r + 8) * N + col]     = v2;
                    C[(long)(r + 8) * N + col + 1] = v3;
                }
            }
        }
    }
}

// ---------------------------------------------------------------------------
// _H epilogue (exact replication of reference index gymnastics).
// ---------------------------------------------------------------------------
__global__ void k_h(const float* __restrict__ q, const float* __restrict__ w,
                    float* __restrict__ hq) {
    const int i  = blockIdx.x;   // 0..31
    const int l2 = threadIdx.x;  // 0..255
    __shared__ int   s_ind[LL];
    __shared__ float s_sel[LL * 4];

    const int rsel = l2 >> 6;
    const int lb   = (l2 & 63) * 4;

    const float w0 = w[(i * LL + l2) * RR + 0];
    const float w1 = w[(i * LL + l2) * RR + 1];
    const float w2 = w[(i * LL + l2) * RR + 2];
    const float w3 = w[(i * LL + l2) * RR + 3];

    float best = -3.402823466e38f;
    int bk = 0;
    const int nb = (64 * i) & 511;
    for (int k = 0; k < 64; ++k) {
        int n  = (nb + k) & 511;
        int bp = n >> 4, a = n & 15;
        int sbp = (bp >> 2) + ((bp & 3) << 3);
        const float* qp = q + ((long)(sbp * LL + lb) * AA + a) * RR + rsel;
        float u = qp[0] * w0 + qp[64] * w1 + qp[128] * w2 + qp[192] * w3;
        if (u > best) { best = u; bk = k; }
    }
    s_ind[l2] = bk;
    {
        int n  = (nb + bk) & 511;
        int bp = n >> 4, a = n & 15;
        int sbp = (bp >> 2) + ((bp & 3) << 3);
        const float* qp = q + ((long)(sbp * LL + lb) * AA + a) * RR + rsel;
        s_sel[l2 * 4 + 0] = qp[0];
        s_sel[l2 * 4 + 1] = qp[64];
        s_sel[l2 * 4 + 2] = qp[128];
        s_sel[l2 * 4 + 3] = qp[192];
    }
    __syncthreads();

    int key = bk, pos = 0;
    for (int j = 0; j < LL; ++j) {
        int kj = s_ind[j];
        pos += (kj < key) || (kj == key && j < l2);
    }
    float* o = hq + (long)(i * LL + pos) * 4;
    o[0] = s_sel[l2 * 4 + 0];
    o[1] = s_sel[l2 * 4 + 1];
    o[2] = s_sel[l2 * 4 + 2];
    o[3] = s_sel[l2 * 4 + 3];
}

// ---------------------------------------------------------------------------
// Launch
// ---------------------------------------------------------------------------
extern "C" void kernel_launch(void* const* d_in, const int* in_sizes, int n_in,
                              void* d_out, int out_size) {
    const float* state = (const float*)d_in[0];
    const float* pref  = (const float*)d_in[1];
    const float* W1 = (const float*)d_in[3];
    const float* b1 = (const float*)d_in[4];
    const float* W2 = (const float*)d_in[5];
    const float* b2 = (const float*)d_in[6];
    const float* W3 = (const float*)d_in[7];
    const float* b3 = (const float*)d_in[8];
    const float* W4 = (const float*)d_in[9];
    const float* b4 = (const float*)d_in[10];
    const float* W5 = (const float*)d_in[11];
    const float* b5 = (const float*)d_in[12];

    float* out = (float*)d_out;
    float* hq  = out;                        // [8192, 4]
    float* q   = out + BB * LL * RR;         // [32, 256, 16, 4]

    uint16_t *xh, *xl, *h1, *l1, *h2, *l2s, *h3, *l3, *h4, *l4;
    uint32_t *wph, *wpl;
    cudaGetSymbolAddress((void**)&xh,  g_xh);
    cudaGetSymbolAddress((void**)&xl,  g_xl);
    cudaGetSymbolAddress((void**)&h1,  g_h1);
    cudaGetSymbolAddress((void**)&l1,  g_l1);
    cudaGetSymbolAddress((void**)&h2,  g_h2);
    cudaGetSymbolAddress((void**)&l2s, g_l2);
    cudaGetSymbolAddress((void**)&h3,  g_h3);
    cudaGetSymbolAddress((void**)&l3,  g_l3);
    cudaGetSymbolAddress((void**)&h4,  g_h4);
    cudaGetSymbolAddress((void**)&l4,  g_l4);
    cudaGetSymbolAddress((void**)&wph, g_wph);
    cudaGetSymbolAddress((void**)&wpl, g_wpl);

    cudaFuncSetAttribute(k_gemm<true, true>,   cudaFuncAttributeMaxDynamicSharedMemorySize, SMB);
    cudaFuncSetAttribute(k_gemm<false, false>, cudaFuncAttributeMaxDynamicSharedMemorySize, SMB);

    // weight pair-split (per launch, ~150us; coalesced read + write)
    {
        struct { const float* w; long off; int KW, N, K2; } ws[5] = {
            {W1, PO1, K0, D1, K0P / 2}, {W2, PO2, D1, D2, D1 / 2},
            {W3, PO3, D2, D3, D2 / 2},  {W4, PO4, D3, D4, D3 / 2},
            {W5, PO5, D4, D5, D4 / 2}
        };
        for (int i = 0; i < 5; i++) {
            long total = (long)ws[i].K2 * ws[i].N;
            int blocks = (int)((total + 255) / 256);
            k_wpair<<<blocks, 256>>>(ws[i].w, wph + ws[i].off, wpl + ws[i].off,
                                     ws[i].KW, ws[i].N, total);
        }
    }

    k_concat<<<(M_TOK * K0P + 255) / 256, 256>>>(state, pref, xh, xl);

    {
        dim3 g((D1 + 127) / 128, M_TOK / 128);
        k_gemm<true, true><<<g, 256, SMB>>>(xh, xl, wph + PO1, wpl + PO1, b1,
                                            h1, l1, nullptr, D1, K0P);
    }
    {
        dim3 g((D2 + 127) / 128, M_TOK / 128);
        k_gemm<true, true><<<g, 256, SMB>>>(h1, l1, wph + PO2, wpl + PO2, b2,
                                            h2, l2s, nullptr, D2, D1);
    }
    {
        dim3 g((D3 + 127) / 128, M_TOK / 128);
        k_gemm<true, true><<<g, 256, SMB>>>(h2, l2s, wph + PO3, wpl + PO3, b3,
                                            h3, l3, nullptr, D3, D2);
    }
    {
        dim3 g((D4 + 127) / 128, M_TOK / 128);
        k_gemm<true, true><<<g, 256, SMB>>>(h3, l3, wph + PO4, wpl + PO4, b4,
                                            h4, l4, nullptr, D4, D3);
    }
    {
        dim3 g(1, M_TOK / 128);
        k_gemm<false, false><<<g, 256, SMB>>>(h4, l4, wph + PO5, wpl + PO5, b5,
                                              nullptr, nullptr, q, D5, D4);
    }

    k_h<<<BB, LL>>>(q, pref, hq);
}